// round 11
// baseline (speedup 1.0000x reference)
#include <cuda_runtime.h>
#include <cuda_bf16.h>
#include <math.h>

#define BATCH   32
#define NTOK    197
#define DIM     768
#define HEADS   12
#define HD      64
#define MLPD    3072
#define DEPTH   12
#define ROWS    (BATCH*NTOK)     // 6304
#define NPATCH  196
#define PROWS   (BATCH*NPATCH)   // 6272
#define ATTN_SCALE 0.125f
#define MPAD    6400             // padded M for split activation buffers (50*128)

// ---------------- scratch (no cudaMalloc allowed) ----------------
__device__ float    g_h   [ROWS*DIM];
__device__ float    g_qkv [ROWS*3*DIM];      // also reused as patch-gemm fp32 output
__device__ unsigned gAh[384*MPAD],  gAl[384*MPAD];     // split activations, K<=768
__device__ unsigned gMh[1536*MPAD], gMl[1536*MPAD];    // split MLP mid, K=3072
__device__ unsigned gWh[1179648],   gWl[1179648];      // split weights (max 384*3072)

// ---------------- helpers ----------------
__device__ __forceinline__ float gelu_exact(float x) {
    return 0.5f * x * (1.0f + erff(x * 0.70710678118654752f));
}
// pack two floats as bf16x2: first arg -> low 16 bits (even k)
__device__ __forceinline__ unsigned pack2bf(float lo, float hi) {
    unsigned r;
    asm("cvt.rn.bf16x2.f32 %0, %1, %2;" : "=r"(r) : "f"(hi), "f"(lo));
    return r;
}
__device__ __forceinline__ float bf16hi_of(float x) {
    __nv_bfloat16 h = __float2bfloat16_rn(x);
    return __bfloat162float(h);
}
__device__ __forceinline__ void cpasync16(unsigned sdst, const void* g) {
    asm volatile("cp.async.cg.shared.global [%0], [%1], 16;" :: "r"(sdst), "l"(g));
}

// block reduce over 256 threads (attn). do_max=true -> max else sum.
__device__ __forceinline__ float blk_reduce256(float v, bool do_max, float* red) {
    #pragma unroll
    for (int off = 16; off; off >>= 1) {
        float o = __shfl_xor_sync(0xffffffffu, v, off);
        v = do_max ? fmaxf(v, o) : (v + o);
    }
    int w = threadIdx.x >> 5;
    if ((threadIdx.x & 31) == 0) red[w] = v;
    __syncthreads();
    if (threadIdx.x < 32) {
        v = red[threadIdx.x & 7];
        #pragma unroll
        for (int off = 4; off; off >>= 1) {
            float o = __shfl_xor_sync(0xffffffffu, v, off);
            v = do_max ? fmaxf(v, o) : (v + o);
        }
        if (threadIdx.x == 0) red[0] = v;
    }
    __syncthreads();
    float r = red[0];
    __syncthreads();
    return r;
}

// ---------------- patch gather, split output [k2][m] ----------------
__global__ void gather_split_kernel(const float* __restrict__ x,
                                    unsigned* __restrict__ hiT, unsigned* __restrict__ loT) {
    int idx = blockIdx.x * blockDim.x + threadIdx.x;
    int total = 384 * PROWS;
    if (idx >= total) return;
    int k2 = idx / PROWS, m = idx - k2 * PROWS;
    int b = m / NPATCH, t = m - b * NPATCH;
    int ph = t / 14, pw = t - ph * 14;
    int k = 2 * k2;
    int c = k >> 8, r = k & 255;
    int py = r >> 4, px = r & 15;           // px even
    const float* src = x + (((long)b * 3 + c) * 224 + (ph * 16 + py)) * 224 + pw * 16 + px;
    float v0 = src[0], v1 = src[1];
    float h0 = bf16hi_of(v0), h1 = bf16hi_of(v1);
    hiT[(long)k2 * MPAD + m] = pack2bf(h0, h1);
    loT[(long)k2 * MPAD + m] = pack2bf(v0 - h0, v1 - h1);
}

// ---------------- assemble h = [cls ; tok] + pos ----------------
__global__ void embed_kernel(const float* __restrict__ tok, const float* __restrict__ cls,
                             const float* __restrict__ pos, float* __restrict__ h) {
    int idx = blockIdx.x * blockDim.x + threadIdx.x;
    int total = ROWS * DIM;
    if (idx >= total) return;
    int rd = idx % (NTOK * DIM);
    int b  = idx / (NTOK * DIM);
    int n  = rd / DIM, d = rd - n * DIM;
    float base = (n == 0) ? cls[d] : tok[((long)b * NPATCH + (n - 1)) * DIM + d];
    h[idx] = base + pos[n * DIM + d];
}

// ---------------- layernorm with split-transposed output ----------------
// block handles 32 rows; phase1 per-row stats (warp per 4 rows), phase2 coalesced
// [k2][m] split writes (re-reads hit L1).
__global__ __launch_bounds__(256) void ln_split_kernel(
        const float* __restrict__ x, long row_stride,
        const float* __restrict__ w, const float* __restrict__ b,
        unsigned* __restrict__ hiT, unsigned* __restrict__ loT) {
    __shared__ float smu[32], sinv[32];
    int r0 = blockIdx.x * 32;
    int tid = threadIdx.x, warp = tid >> 5, lane = tid & 31;
    #pragma unroll
    for (int rr = 0; rr < 4; rr++) {
        int rloc = warp * 4 + rr;
        const float* xr = x + (long)(r0 + rloc) * row_stride;
        float s = 0.f, ss = 0.f;
        #pragma unroll
        for (int i = 0; i < 24; i++) { float v = xr[lane + 32 * i]; s += v; ss += v * v; }
        #pragma unroll
        for (int off = 16; off; off >>= 1) {
            s  += __shfl_xor_sync(0xffffffffu, s,  off);
            ss += __shfl_xor_sync(0xffffffffu, ss, off);
        }
        if (lane == 0) {
            float mu = s * (1.0f / 768.0f);
            float var = ss * (1.0f / 768.0f) - mu * mu;
            smu[rloc] = mu;
            sinv[rloc] = rsqrtf(var + 1e-5f);
        }
    }
    __syncthreads();
    #pragma unroll
    for (int i = 0; i < 48; i++) {
        int idx = tid + 256 * i;          // 0..12287 : k2 (384) x j (32)
        int k2 = idx >> 5, j = idx & 31;
        int row = r0 + j;
        const float* xr = x + (long)row * row_stride + 2 * k2;
        float mu = smu[j], inv = sinv[j];
        float y0 = (xr[0] - mu) * inv * w[2 * k2]     + b[2 * k2];
        float y1 = (xr[1] - mu) * inv * w[2 * k2 + 1] + b[2 * k2 + 1];
        float h0 = bf16hi_of(y0), h1 = bf16hi_of(y1);
        hiT[(long)k2 * MPAD + row] = pack2bf(h0, h1);
        loT[(long)k2 * MPAD + row] = pack2bf(y0 - h0, y1 - h1);
    }
}

// ---------------- weight split+transpose: src[N][K] fp32 -> hiT/loT [K/2][NPAD] ----------------
__global__ __launch_bounds__(256) void wsplit_kernel(
        const float* __restrict__ src, unsigned* __restrict__ hiT, unsigned* __restrict__ loT,
        int N, int K, int NPAD) {
    __shared__ unsigned th[32][33], tl[32][33];
    int k20 = blockIdx.x * 32, n0 = blockIdx.y * 32;
    int tx = threadIdx.x & 31, ty = threadIdx.x >> 5;   // ty 0..7
    #pragma unroll
    for (int i = 0; i < 4; i++) {
        int nl = ty + i * 8;
        int n = n0 + nl, k2 = k20 + tx;
        float v0 = 0.f, v1 = 0.f;
        if (n < N) {
            const float* s = src + (long)n * K + 2 * k2;
            v0 = s[0]; v1 = s[1];
        }
        float h0 = bf16hi_of(v0), h1 = bf16hi_of(v1);
        th[tx][nl] = pack2bf(h0, h1);
        tl[tx][nl] = pack2bf(v0 - h0, v1 - h1);
    }
    __syncthreads();
    #pragma unroll
    for (int i = 0; i < 4; i++) {
        int k2l = ty + i * 8;
        long o = (long)(k20 + k2l) * NPAD + n0 + tx;
        hiT[o] = th[k2l][tx];
        loT[o] = tl[k2l][tx];
    }
}

// ---------------- 2-split BF16 tensor-core GEMM (pre-split operands) ----------------
// C[M,N] = A[M,K] @ W[N,K]^T, operands as hi/lo bf16x2 in [k2][m] / [k2][n] layout.
// block 128x128x16, 8 warps, warp 64x32 via m16n8k16; 3-term compensation.
#define BM 128
#define BN 128
#define SPITCH 136
#define SMARR  (8*SPITCH)          // one array-slab per stage

__global__ __launch_bounds__(256) void gemm_tc_kernel(
        const unsigned* __restrict__ AhiT, const unsigned* __restrict__ AloT, int pitchA,
        const unsigned* __restrict__ WhiT, const unsigned* __restrict__ WloT, int pitchW,
        const float* __restrict__ bias, const float* __restrict__ resid,
        float* __restrict__ C,
        unsigned* __restrict__ ChiT, unsigned* __restrict__ CloT, int pitchC,
        int M, int N, int K, int act, int splitout) {
    __shared__ unsigned smbuf[2 * 4 * SMARR];

    int bm = blockIdx.y * BM;
    int bn = blockIdx.x * BN;
    int tid  = threadIdx.x;
    int warp = tid >> 5;
    int lane = tid & 31;
    int g    = lane >> 2;
    int t4   = lane & 3;
    int wm = (warp & 1) * 64;
    int wn = (warp >> 1) * 32;

    // async-copy coords: thread covers one 16B chunk per array per tile
    int cr = tid >> 5;              // k2 row 0..7
    int cc = (lane) << 2;           // uint col 0..124
    const unsigned* gA0 = AhiT + (long)cr * pitchA + bm + cc;
    const unsigned* gA1 = AloT + (long)cr * pitchA + bm + cc;
    const unsigned* gW0 = WhiT + (long)cr * pitchW + bn + cc;
    const unsigned* gW1 = WloT + (long)cr * pitchW + bn + cc;
    unsigned sbase = (unsigned)__cvta_generic_to_shared(smbuf);
    unsigned sA0 = sbase + (unsigned)((0 * SMARR + cr * SPITCH + cc) * 4);
    unsigned sA1 = sbase + (unsigned)((1 * SMARR + cr * SPITCH + cc) * 4);
    unsigned sW0 = sbase + (unsigned)((2 * SMARR + cr * SPITCH + cc) * 4);
    unsigned sW1 = sbase + (unsigned)((3 * SMARR + cr * SPITCH + cc) * 4);
    const unsigned stagestep = 4 * SMARR * 4;

    float acc[4][4][4];
    #pragma unroll
    for (int i = 0; i < 4; i++)
        #pragma unroll
        for (int j = 0; j < 4; j++)
            #pragma unroll
            for (int c = 0; c < 4; c++) acc[i][j][c] = 0.f;

    int T = K >> 4;   // k16 tiles
    // prologue: issue tile 0 into stage 0
    {
        cpasync16(sA0, gA0); cpasync16(sA1, gA1);
        cpasync16(sW0, gW0); cpasync16(sW1, gW1);
        asm volatile("cp.async.commit_group;");
    }

    for (int t = 0; t < T; t++) {
        asm volatile("cp.async.wait_group 0;");
        __syncthreads();
        int st = t & 1;
        if (t + 1 < T) {
            long go = (long)(t + 1) * 8;
            unsigned so = (unsigned)((t + 1) & 1) * stagestep;
            cpasync16(sA0 + so, gA0 + go * pitchA);
            cpasync16(sA1 + so, gA1 + go * pitchA);
            cpasync16(sW0 + so, gW0 + go * pitchW);
            cpasync16(sW1 + so, gW1 + go * pitchW);
            asm volatile("cp.async.commit_group;");
        }
        const unsigned* base = smbuf + st * 4 * SMARR;
        #define AH_(k2,m) base[0*SMARR + (k2)*SPITCH + (m)]
        #define AL_(k2,m) base[1*SMARR + (k2)*SPITCH + (m)]
        #define WH_(k2,m) base[2*SMARR + (k2)*SPITCH + (m)]
        #define WL_(k2,m) base[3*SMARR + (k2)*SPITCH + (m)]

        unsigned afH[4][4], afL[4][4];
        unsigned bfH[4][2], bfL[4][2];
        #pragma unroll
        for (int mt = 0; mt < 4; mt++) {
            int m0 = wm + mt * 16;
            afH[mt][0] = AH_(t4    , m0 + g    );
            afH[mt][1] = AH_(t4    , m0 + g + 8);
            afH[mt][2] = AH_(t4 + 4, m0 + g    );
            afH[mt][3] = AH_(t4 + 4, m0 + g + 8);
            afL[mt][0] = AL_(t4    , m0 + g    );
            afL[mt][1] = AL_(t4    , m0 + g + 8);
            afL[mt][2] = AL_(t4 + 4, m0 + g    );
            afL[mt][3] = AL_(t4 + 4, m0 + g + 8);
        }
        #pragma unroll
        for (int nt = 0; nt < 4; nt++) {
            int n0 = wn + nt * 8;
            bfH[nt][0] = WH_(t4    , n0 + g);
            bfH[nt][1] = WH_(t4 + 4, n0 + g);
            bfL[nt][0] = WL_(t4    , n0 + g);
            bfL[nt][1] = WL_(t4 + 4, n0 + g);
        }
        #pragma unroll
        for (int mt = 0; mt < 4; mt++)
            #pragma unroll
            for (int nt = 0; nt < 4; nt++) {
                asm volatile(
                    "mma.sync.aligned.m16n8k16.row.col.f32.bf16.bf16.f32 "
                    "{%0,%1,%2,%3}, {%4,%5,%6,%7}, {%8,%9}, {%0,%1,%2,%3};"
                    : "+f"(acc[mt][nt][0]), "+f"(acc[mt][nt][1]),
                      "+f"(acc[mt][nt][2]), "+f"(acc[mt][nt][3])
                    : "r"(afL[mt][0]), "r"(afL[mt][1]), "r"(afL[mt][2]), "r"(afL[mt][3]),
                      "r"(bfH[nt][0]), "r"(bfH[nt][1]));
                asm volatile(
                    "mma.sync.aligned.m16n8k16.row.col.f32.bf16.bf16.f32 "
                    "{%0,%1,%2,%3}, {%4,%5,%6,%7}, {%8,%9}, {%0,%1,%2,%3};"
                    : "+f"(acc[mt][nt][0]), "+f"(acc[mt][nt][1]),
                      "+f"(acc[mt][nt][2]), "+f"(acc[mt][nt][3])
                    : "r"(afH[mt][0]), "r"(afH[mt][1]), "r"(afH[mt][2]), "r"(afH[mt][3]),
                      "r"(bfL[nt][0]), "r"(bfL[nt][1]));
                asm volatile(
                    "mma.sync.aligned.m16n8k16.row.col.f32.bf16.bf16.f32 "
                    "{%0,%1,%2,%3}, {%4,%5,%6,%7}, {%8,%9}, {%0,%1,%2,%3};"
                    : "+f"(acc[mt][nt][0]), "+f"(acc[mt][nt][1]),
                      "+f"(acc[mt][nt][2]), "+f"(acc[mt][nt][3])
                    : "r"(afH[mt][0]), "r"(afH[mt][1]), "r"(afH[mt][2]), "r"(afH[mt][3]),
                      "r"(bfH[nt][0]), "r"(bfH[nt][1]));
            }
    }

    // epilogue
    #pragma unroll
    for (int mt = 0; mt < 4; mt++) {
        int row0 = bm + wm + mt * 16 + g;
        int row1 = row0 + 8;
        #pragma unroll
        for (int nt = 0; nt < 4; nt++) {
            int col = bn + wn + nt * 8 + t4 * 2;
            float bs0 = 0.f, bs1 = 0.f;
            if (bias && col < N)     bs0 = bias[col];
            if (bias && col + 1 < N) bs1 = bias[col + 1];
            #pragma unroll
            for (int half = 0; half < 2; half++) {
                int row = half ? row1 : row0;
                if (row >= M) continue;
                float v0 = acc[mt][nt][half * 2 + 0] + bs0;
                float v1 = acc[mt][nt][half * 2 + 1] + bs1;
                if (resid) {
                    if (col < N)     v0 += resid[(long)row * N + col];
                    if (col + 1 < N) v1 += resid[(long)row * N + col + 1];
                }
                if (act == 1) { v0 = gelu_exact(v0); v1 = gelu_exact(v1); }
                if (splitout) {
                    if (col + 1 < N || col < N) {
                        float h0 = bf16hi_of(v0), h1 = bf16hi_of(v1);
                        long o = (long)(col >> 1) * pitchC + row;
                        ChiT[o] = pack2bf(h0, h1);
                        CloT[o] = pack2bf(v0 - h0, v1 - h1);
                    }
                } else {
                    if (col < N)     C[(long)row * N + col]     = v0;
                    if (col + 1 < N) C[(long)row * N + col + 1] = v1;
                }
            }
        }
    }
}

// ---------------- attention: one block per (b,h), split [k2][m] output ----------------
#define ATTN_SMEM_FLOATS (NTOK*HD*2 + 64 + 208 + 256 + 8)
__global__ __launch_bounds__(256) void attn_kernel(
        const float* __restrict__ qkv,
        unsigned* __restrict__ ohiT, unsigned* __restrict__ oloT,
        const float* __restrict__ alpha, const float* __restrict__ beta,
        const float* __restrict__ gamma, int poly) {
    extern __shared__ float sh[];
    float* Ks     = sh;
    float* Vs     = Ks + NTOK * HD;
    float* qs     = Vs + NTOK * HD;
    float* scores = qs + 64;
    float* part   = scores + 208;
    float* red    = part + 256;

    int b = blockIdx.x / HEADS;
    int hh = blockIdx.x - b * HEADS;
    int tid = threadIdx.x;

    const float* kbase = qkv + (long)(b * NTOK) * (3 * DIM) + DIM + hh * HD;
    const float* vbase = kbase + DIM;
    for (int i = tid; i < NTOK * (HD / 4); i += 256) {
        int n = i >> 4, d4 = (i & 15) << 2;
        ((float4*)Ks)[i] = *(const float4*)(kbase + (long)n * (3 * DIM) + d4);
        ((float4*)Vs)[i] = *(const float4*)(vbase + (long)n * (3 * DIM) + d4);
    }
    float ah = alpha[hh], bh = beta[hh], gh = gamma[hh];
    __syncthreads();

    for (int n = 0; n < NTOK; n++) {
        const float* qrow = qkv + (long)(b * NTOK + n) * (3 * DIM) + hh * HD;
        if (tid < HD) qs[tid] = qrow[tid];
        __syncthreads();

        float sraw = 0.f;
        if (tid < NTOK) {
            const float* kr = Ks + tid * HD;
            float d0 = 0.f;
            #pragma unroll 16
            for (int d = 0; d < HD; d++) d0 = fmaf(qs[d], kr[d], d0);
            sraw = d0 * ATTN_SCALE;
        }

        float denom;
        if (poly) {
            float val = 0.f;
            if (tid < NTOK) {
                val = fmaxf(fmaf(ah * sraw, sraw, fmaf(bh, sraw, gh)), 0.f);
                scores[tid] = val;
            }
            denom = blk_reduce256(tid < NTOK ? val : 0.f, false, red) + 1e-6f;
        } else {
            float mx = blk_reduce256(tid < NTOK ? sraw : -1e30f, true, red);
            float p = 0.f;
            if (tid < NTOK) { p = __expf(sraw - mx); scores[tid] = p; }
            denom = blk_reduce256(p, false, red);
        }
        float inv = 1.0f / denom;

        int ch = tid >> 6, d = tid & 63;
        float a0 = 0.f;
        int m0 = ch * 50, m1 = m0 + 50; if (m1 > NTOK) m1 = NTOK;
        #pragma unroll 4
        for (int m = m0; m < m1; m++) a0 = fmaf(scores[m], Vs[m * HD + d], a0);
        part[ch * 64 + d] = a0;
        __syncthreads();
        if (tid < 32) {
            int d0 = 2 * tid;
            float t0 = (part[d0]   + part[64 + d0]   + part[128 + d0]   + part[192 + d0])   * inv;
            float t1 = (part[d0+1] + part[64 + d0+1] + part[128 + d0+1] + part[192 + d0+1]) * inv;
            float h0 = bf16hi_of(t0), h1 = bf16hi_of(t1);
            long m = (long)(b * NTOK + n);
            long o = (long)(hh * 32 + tid) * MPAD + m;
            ohiT[o] = pack2bf(h0, h1);
            oloT[o] = pack2bf(t0 - h0, t1 - h1);
        }
        __syncthreads();
    }
}

// ---------------- host ----------------
static inline dim3 gemm_grid(int M, int NPADv) {
    return dim3(NPADv / BN, (M + BM - 1) / BM);
}

extern "C" void kernel_launch(void* const* d_in, const int* in_sizes, int n_in,
                              void* d_out, int out_size) {
    const float* x        = (const float*)d_in[0];
    const float* patch_w  = (const float*)d_in[1];
    const float* patch_b  = (const float*)d_in[2];
    const float* cls_tok  = (const float*)d_in[3];
    const float* pos_emb  = (const float*)d_in[4];
    const float* ln1_w    = (const float*)d_in[5];
    const float* ln1_b    = (const float*)d_in[6];
    const float* qkv_w    = (const float*)d_in[7];
    const float* proj_w   = (const float*)d_in[8];
    const float* proj_b   = (const float*)d_in[9];
    const float* ln2_w    = (const float*)d_in[10];
    const float* ln2_b    = (const float*)d_in[11];
    const float* mlp_w1   = (const float*)d_in[12];
    const float* mlp_b1   = (const float*)d_in[13];
    const float* mlp_w2   = (const float*)d_in[14];
    const float* mlp_b2   = (const float*)d_in[15];
    const float* alpha    = (const float*)d_in[16];
    const float* beta     = (const float*)d_in[17];
    const float* gamma    = (const float*)d_in[18];
    const float* norm_w   = (const float*)d_in[19];
    const float* norm_b   = (const float*)d_in[20];
    const float* head_w   = (const float*)d_in[21];
    const float* head_b   = (const float*)d_in[22];
    float* out = (float*)d_out;

    float *hh, *qkvb;
    unsigned *ah, *al, *mh, *ml, *wh, *wl;
    cudaGetSymbolAddress((void**)&hh,   g_h);
    cudaGetSymbolAddress((void**)&qkvb, g_qkv);
    cudaGetSymbolAddress((void**)&ah,   gAh);
    cudaGetSymbolAddress((void**)&al,   gAl);
    cudaGetSymbolAddress((void**)&mh,   gMh);
    cudaGetSymbolAddress((void**)&ml,   gMl);
    cudaGetSymbolAddress((void**)&wh,   gWh);
    cudaGetSymbolAddress((void**)&wl,   gWl);

    const int attn_smem = ATTN_SMEM_FLOATS * sizeof(float);
    cudaFuncSetAttribute(attn_kernel, cudaFuncAttributeMaxDynamicSharedMemorySize, attn_smem);

    // 1) patchify (split) -> patch GEMM (fp32 out) -> embed
    {
        int total = 384 * PROWS;
        gather_split_kernel<<<(total + 255) / 256, 256>>>(x, ah, al);
        wsplit_kernel<<<dim3(768 / 64, (768 + 31) / 32), 256>>>(patch_w, wh, wl, 768, 768, 768);
        gemm_tc_kernel<<<gemm_grid(PROWS, 768), 256>>>(ah, al, MPAD, wh, wl, 768,
                                                       patch_b, nullptr, qkvb,
                                                       nullptr, nullptr, 0,
                                                       PROWS, 768, 768, 0, 0);
        int tot2 = ROWS * DIM;
        embed_kernel<<<(tot2 + 255) / 256, 256>>>(qkvb, cls_tok, pos_emb, hh);
    }

    // 2) transformer layers
    for (int i = 0; i < DEPTH; i++) {
        int poly = (i % 2 == 0) ? 1 : 0;   // MASK = (T,F,T,F,...)
        // --- attention block ---
        ln_split_kernel<<<ROWS / 32, 256>>>(hh, DIM, ln1_w + (long)i * DIM, ln1_b + (long)i * DIM, ah, al);
        wsplit_kernel<<<dim3(768 / 64, 2304 / 32), 256>>>(qkv_w + (long)i * 3 * DIM * DIM, wh, wl, 2304, 768, 2304);
        gemm_tc_kernel<<<gemm_grid(ROWS, 2304), 256>>>(ah, al, MPAD, wh, wl, 2304,
                                                       nullptr, nullptr, qkvb,
                                                       nullptr, nullptr, 0,
                                                       ROWS, 2304, 768, 0, 0);
        attn_kernel<<<BATCH * HEADS, 256, attn_smem>>>(qkvb, ah, al,
                                                       alpha + (long)i * HEADS,
                                                       beta  + (long)i * HEADS,
                                                       gamma + (long)i * HEADS, poly);
        wsplit_kernel<<<dim3(768 / 64, 768 / 32), 256>>>(proj_w + (long)i * DIM * DIM, wh, wl, 768, 768, 768);
        gemm_tc_kernel<<<gemm_grid(ROWS, 768), 256>>>(ah, al, MPAD, wh, wl, 768,
                                                      proj_b + (long)i * DIM, hh, hh,
                                                      nullptr, nullptr, 0,
                                                      ROWS, 768, 768, 0, 0);
        // --- MLP block ---
        ln_split_kernel<<<ROWS / 32, 256>>>(hh, DIM, ln2_w + (long)i * DIM, ln2_b + (long)i * DIM, ah, al);
        wsplit_kernel<<<dim3(768 / 64, 3072 / 32), 256>>>(mlp_w1 + (long)i * MLPD * DIM, wh, wl, 3072, 768, 3072);
        gemm_tc_kernel<<<gemm_grid(ROWS, 3072), 256>>>(ah, al, MPAD, wh, wl, 3072,
                                                       mlp_b1 + (long)i * MLPD, nullptr, nullptr,
                                                       mh, ml, MPAD,
                                                       ROWS, 3072, 768, 1 /*gelu*/, 1 /*split*/);
        wsplit_kernel<<<dim3(3072 / 64, 768 / 32), 256>>>(mlp_w2 + (long)i * DIM * MLPD, wh, wl, 768, 3072, 768);
        gemm_tc_kernel<<<gemm_grid(ROWS, 768), 256>>>(mh, ml, MPAD, wh, wl, 768,
                                                      mlp_b2 + (long)i * DIM, hh, hh,
                                                      nullptr, nullptr, 0,
                                                      ROWS, 768, 3072, 0, 0);
    }

    // 3) final LN (cls rows, stride NTOK*DIM) + head
    ln_split_kernel<<<1, 256>>>(hh, (long)NTOK * DIM, norm_w, norm_b, ah, al);
    wsplit_kernel<<<dim3(768 / 64, (1000 + 31) / 32), 256>>>(head_w, wh, wl, 1000, 768, 1024);
    gemm_tc_kernel<<<gemm_grid(BATCH, 1024), 256>>>(ah, al, MPAD, wh, wl, 1024,
                                                    head_b, nullptr, out,
                                                    nullptr, nullptr, 0,
                                                    BATCH, 1000, 768, 0, 0);
}

// round 12
// speedup vs baseline: 1.8597x; 1.8597x over previous
#include <cuda_runtime.h>
#include <cuda_fp16.h>
#include <math.h>

#define BATCH   32
#define NTOK    197
#define DIM     768
#define HEADS   12
#define HD      64
#define MLPD    3072
#define DEPTH   12
#define ROWS    (BATCH*NTOK)     // 6304
#define NPATCH  196
#define PROWS   (BATCH*NPATCH)   // 6272
#define ATTN_SCALE 0.125f

// ---------------- scratch (no cudaMalloc allowed) ----------------
__device__ float g_patches[PROWS*DIM];
__device__ float g_h     [ROWS*DIM];
__device__ float g_ln    [ROWS*DIM];
__device__ float g_qkv   [ROWS*3*DIM];
__device__ float g_attno [ROWS*DIM];
__device__ float g_mlp   [ROWS*MLPD];
__device__ float g_cls   [BATCH*DIM];

// ---------------- helpers ----------------
__device__ __forceinline__ float gelu_exact(float x) {
    return 0.5f * x * (1.0f + erff(x * 0.70710678118654752f));
}
// pack two floats as f16x2: first arg -> low 16 bits (even k)
__device__ __forceinline__ unsigned pack2h(float lo, float hi) {
    unsigned r;
    asm("cvt.rn.f16x2.f32 %0, %1, %2;" : "=r"(r) : "f"(hi), "f"(lo));
    return r;
}
__device__ __forceinline__ float f16hi_of(float x) {
    __half h = __float2half_rn(x);
    return __half2float(h);
}

// block reduce over 256 threads. do_max=true -> max else sum.
__device__ __forceinline__ float blk_reduce256(float v, bool do_max, float* red) {
    #pragma unroll
    for (int off = 16; off; off >>= 1) {
        float o = __shfl_xor_sync(0xffffffffu, v, off);
        v = do_max ? fmaxf(v, o) : (v + o);
    }
    int w = threadIdx.x >> 5;
    if ((threadIdx.x & 31) == 0) red[w] = v;
    __syncthreads();
    if (threadIdx.x < 32) {
        v = red[threadIdx.x & 7];
        #pragma unroll
        for (int off = 4; off; off >>= 1) {
            float o = __shfl_xor_sync(0xffffffffu, v, off);
            v = do_max ? fmaxf(v, o) : (v + o);
        }
        if (threadIdx.x == 0) red[0] = v;
    }
    __syncthreads();
    float r = red[0];
    __syncthreads();
    return r;
}

// ---------------- patch gather ----------------
__global__ void gather_patches_kernel(const float* __restrict__ x, float* __restrict__ P) {
    int idx = blockIdx.x * blockDim.x + threadIdx.x;
    int total = PROWS * DIM;
    if (idx >= total) return;
    int m = idx / DIM, k = idx - m * DIM;
    int b = m / NPATCH, t = m - b * NPATCH;
    int ph = t / 14, pw = t - ph * 14;
    int c = k >> 8, r = k & 255;
    int py = r >> 4, px = r & 15;
    int h = ph * 16 + py, w = pw * 16 + px;
    P[idx] = x[(((long)b * 3 + c) * 224 + h) * 224 + w];
}

// ---------------- assemble h = [cls ; tok] + pos ----------------
__global__ void embed_kernel(const float* __restrict__ tok, const float* __restrict__ cls,
                             const float* __restrict__ pos, float* __restrict__ h) {
    int idx = blockIdx.x * blockDim.x + threadIdx.x;
    int total = ROWS * DIM;
    if (idx >= total) return;
    int rd = idx % (NTOK * DIM);
    int b  = idx / (NTOK * DIM);
    int n  = rd / DIM, d = rd - n * DIM;
    float base = (n == 0) ? cls[d] : tok[((long)b * NPATCH + (n - 1)) * DIM + d];
    h[idx] = base + pos[n * DIM + d];
}

// ---------------- layernorm ----------------
__global__ void ln_kernel(const float* __restrict__ x, long row_stride,
                          const float* __restrict__ w, const float* __restrict__ b,
                          float* __restrict__ y) {
    __shared__ float red[8];
    long row = blockIdx.x;
    const float* xr = x + row * row_stride;
    int tid = threadIdx.x;
    float v[3], s = 0.f, ss = 0.f;
    #pragma unroll
    for (int i = 0; i < 3; i++) {
        float t = xr[tid + i * 256];
        v[i] = t; s += t; ss += t * t;
    }
    s  = blk_reduce256(s,  false, red);
    ss = blk_reduce256(ss, false, red);
    float mu  = s * (1.0f / 768.0f);
    float var = ss * (1.0f / 768.0f) - mu * mu;
    float inv = rsqrtf(var + 1e-5f);
    #pragma unroll
    for (int i = 0; i < 3; i++) {
        int d = tid + i * 256;
        y[row * DIM + d] = (v[i] - mu) * inv * w[d] + b[d];
    }
}

// ---------------- 2-term FP16-split tensor-core GEMM ----------------
// C[M,N] = A[M,K] @ W[N,K]^T (+bias)(+resid)(gelu)
// block tile 128x128x16, 8 warps, each warp 64x32 via m16n8k16 f16 mma.
// A = aH + aL (both fp16); W quantized to fp16 once.
// product = (aH + aL) * wq  ->  error only from W quantization (~2^-12).
#define BM 128
#define BN 128
#define BK 16
#define SPITCH 136   // pitch in uint32; 136 % 32 == 8 -> conflict-free frag loads

__global__ __launch_bounds__(256) void gemm_tc_kernel(
        const float* __restrict__ A, const float* __restrict__ W,
        const float* __restrict__ bias, const float* __restrict__ resid,
        float* __restrict__ C, int M, int N, int K, int act /*1=gelu*/) {
    // packed f16x2 along k: index [k2][m], k2 = k/2 in 0..7
    __shared__ unsigned AsH[8][SPITCH];
    __shared__ unsigned AsL[8][SPITCH];
    __shared__ unsigned Ws [8][SPITCH];

    int bm = blockIdx.y * BM;
    int bn = blockIdx.x * BN;
    int tid  = threadIdx.x;
    int warp = tid >> 5;
    int lane = tid & 31;
    int g    = lane >> 2;    // 0..7
    int t4   = lane & 3;     // 0..3

    int wm = (warp & 1) * 64;
    int wn = (warp >> 1) * 32;

    // global-load coords (2 float4 per array per tile)
    int lm0 = tid >> 2;                 // 0..63   (it=0)
    int lm1 = (tid + 256) >> 2;         // 64..127 (it=1)
    int lk4 = (tid & 3) << 2;           // 0,4,8,12

    float acc[4][4][4];
    #pragma unroll
    for (int i = 0; i < 4; i++)
        #pragma unroll
        for (int j = 0; j < 4; j++)
            #pragma unroll
            for (int c = 0; c < 4; c++) acc[i][j][c] = 0.f;

    // prefetch tile 0
    float4 pA[2], pW[2];
    {
        int gr0 = bm + lm0, gr1 = bm + lm1;
        pA[0] = (gr0 < M) ? *(const float4*)(A + (long)gr0 * K + lk4) : make_float4(0,0,0,0);
        pA[1] = (gr1 < M) ? *(const float4*)(A + (long)gr1 * K + lk4) : make_float4(0,0,0,0);
        int gc0 = bn + lm0, gc1 = bn + lm1;
        pW[0] = (gc0 < N) ? *(const float4*)(W + (long)gc0 * K + lk4) : make_float4(0,0,0,0);
        pW[1] = (gc1 < N) ? *(const float4*)(W + (long)gc1 * K + lk4) : make_float4(0,0,0,0);
    }

    int k2base = lk4 >> 1;   // 0,2,4,6

    for (int kt = 0; kt < K; kt += BK) {
        // store prefetched tile into smem (split A, quantize W)
        #pragma unroll
        for (int it = 0; it < 2; it++) {
            int m = it ? lm1 : lm0;
            float av[4] = {pA[it].x, pA[it].y, pA[it].z, pA[it].w};
            float wv[4] = {pW[it].x, pW[it].y, pW[it].z, pW[it].w};
            float ah0 = f16hi_of(av[0]), ah1 = f16hi_of(av[1]);
            float ah2 = f16hi_of(av[2]), ah3 = f16hi_of(av[3]);
            AsH[k2base  ][m] = pack2h(ah0, ah1);
            AsH[k2base+1][m] = pack2h(ah2, ah3);
            AsL[k2base  ][m] = pack2h(av[0]-ah0, av[1]-ah1);
            AsL[k2base+1][m] = pack2h(av[2]-ah2, av[3]-ah3);
            Ws[k2base  ][m] = pack2h(wv[0], wv[1]);
            Ws[k2base+1][m] = pack2h(wv[2], wv[3]);
        }
        __syncthreads();

        // prefetch next tile (overlaps with MMA work below)
        int ktn = kt + BK;
        if (ktn < K) {
            int gr0 = bm + lm0, gr1 = bm + lm1;
            pA[0] = (gr0 < M) ? *(const float4*)(A + (long)gr0 * K + ktn + lk4) : make_float4(0,0,0,0);
            pA[1] = (gr1 < M) ? *(const float4*)(A + (long)gr1 * K + ktn + lk4) : make_float4(0,0,0,0);
            int gc0 = bn + lm0, gc1 = bn + lm1;
            pW[0] = (gc0 < N) ? *(const float4*)(W + (long)gc0 * K + ktn + lk4) : make_float4(0,0,0,0);
            pW[1] = (gc1 < N) ? *(const float4*)(W + (long)gc1 * K + ktn + lk4) : make_float4(0,0,0,0);
        }

        // one k16 step: fragment loads + 2-term compensated MMA
        unsigned afH[4][4], afL[4][4];
        unsigned bf[4][2];
        #pragma unroll
        for (int mt = 0; mt < 4; mt++) {
            int m0 = wm + mt * 16;
            afH[mt][0] = AsH[t4    ][m0 + g    ];
            afH[mt][1] = AsH[t4    ][m0 + g + 8];
            afH[mt][2] = AsH[t4 + 4][m0 + g    ];
            afH[mt][3] = AsH[t4 + 4][m0 + g + 8];
            afL[mt][0] = AsL[t4    ][m0 + g    ];
            afL[mt][1] = AsL[t4    ][m0 + g + 8];
            afL[mt][2] = AsL[t4 + 4][m0 + g    ];
            afL[mt][3] = AsL[t4 + 4][m0 + g + 8];
        }
        #pragma unroll
        for (int nt = 0; nt < 4; nt++) {
            int n0 = wn + nt * 8;
            bf[nt][0] = Ws[t4    ][n0 + g];
            bf[nt][1] = Ws[t4 + 4][n0 + g];
        }
        #pragma unroll
        for (int mt = 0; mt < 4; mt++)
            #pragma unroll
            for (int nt = 0; nt < 4; nt++) {
                asm volatile(
                    "mma.sync.aligned.m16n8k16.row.col.f32.f16.f16.f32 "
                    "{%0,%1,%2,%3}, {%4,%5,%6,%7}, {%8,%9}, {%0,%1,%2,%3};"
                    : "+f"(acc[mt][nt][0]), "+f"(acc[mt][nt][1]),
                      "+f"(acc[mt][nt][2]), "+f"(acc[mt][nt][3])
                    : "r"(afL[mt][0]), "r"(afL[mt][1]), "r"(afL[mt][2]), "r"(afL[mt][3]),
                      "r"(bf[nt][0]), "r"(bf[nt][1]));
                asm volatile(
                    "mma.sync.aligned.m16n8k16.row.col.f32.f16.f16.f32 "
                    "{%0,%1,%2,%3}, {%4,%5,%6,%7}, {%8,%9}, {%0,%1,%2,%3};"
                    : "+f"(acc[mt][nt][0]), "+f"(acc[mt][nt][1]),
                      "+f"(acc[mt][nt][2]), "+f"(acc[mt][nt][3])
                    : "r"(afH[mt][0]), "r"(afH[mt][1]), "r"(afH[mt][2]), "r"(afH[mt][3]),
                      "r"(bf[nt][0]), "r"(bf[nt][1]));
            }
        __syncthreads();
    }

    // epilogue
    #pragma unroll
    for (int mt = 0; mt < 4; mt++) {
        int row0 = bm + wm + mt * 16 + g;
        int row1 = row0 + 8;
        #pragma unroll
        for (int nt = 0; nt < 4; nt++) {
            int col = bn + wn + nt * 8 + t4 * 2;
            float bs0 = 0.f, bs1 = 0.f;
            if (bias && col < N)     bs0 = bias[col];
            if (bias && col + 1 < N) bs1 = bias[col + 1];
            #pragma unroll
            for (int half = 0; half < 2; half++) {
                int row = half ? row1 : row0;
                if (row >= M) continue;
                float v0 = acc[mt][nt][half * 2 + 0] + bs0;
                float v1 = acc[mt][nt][half * 2 + 1] + bs1;
                if (resid) {
                    if (col < N)     v0 += resid[(long)row * N + col];
                    if (col + 1 < N) v1 += resid[(long)row * N + col + 1];
                }
                if (act == 1) { v0 = gelu_exact(v0); v1 = gelu_exact(v1); }
                if (col < N)     C[(long)row * N + col]     = v0;
                if (col + 1 < N) C[(long)row * N + col + 1] = v1;
            }
        }
    }
}

// ---------------- attention: one block per (b,h) ----------------
#define ATTN_SMEM_FLOATS (NTOK*HD*2 + 64 + 208 + 256 + 8)
__global__ __launch_bounds__(256) void attn_kernel(
        const float* __restrict__ qkv, float* __restrict__ o,
        const float* __restrict__ alpha, const float* __restrict__ beta,
        const float* __restrict__ gamma, int poly) {
    extern __shared__ float sh[];
    float* Ks     = sh;
    float* Vs     = Ks + NTOK * HD;
    float* qs     = Vs + NTOK * HD;
    float* scores = qs + 64;
    float* part   = scores + 208;
    float* red    = part + 256;

    int b = blockIdx.x / HEADS;
    int hh = blockIdx.x - b * HEADS;
    int tid = threadIdx.x;

    const float* kbase = qkv + (long)(b * NTOK) * (3 * DIM) + DIM + hh * HD;
    const float* vbase = kbase + DIM;
    for (int i = tid; i < NTOK * (HD / 4); i += 256) {
        int n = i >> 4, d4 = (i & 15) << 2;
        ((float4*)Ks)[i] = *(const float4*)(kbase + (long)n * (3 * DIM) + d4);
        ((float4*)Vs)[i] = *(const float4*)(vbase + (long)n * (3 * DIM) + d4);
    }
    float ah = alpha[hh], bh = beta[hh], gh = gamma[hh];
    __syncthreads();

    for (int n = 0; n < NTOK; n++) {
        const float* qrow = qkv + (long)(b * NTOK + n) * (3 * DIM) + hh * HD;
        if (tid < HD) qs[tid] = qrow[tid];
        __syncthreads();

        float sraw = 0.f;
        if (tid < NTOK) {
            const float* kr = Ks + tid * HD;
            float d0 = 0.f;
            #pragma unroll 16
            for (int d = 0; d < HD; d++) d0 = fmaf(qs[d], kr[d], d0);
            sraw = d0 * ATTN_SCALE;
        }

        float denom;
        if (poly) {
            float val = 0.f;
            if (tid < NTOK) {
                val = fmaxf(fmaf(ah * sraw, sraw, fmaf(bh, sraw, gh)), 0.f);
                scores[tid] = val;
            }
            denom = blk_reduce256(tid < NTOK ? val : 0.f, false, red) + 1e-6f;
        } else {
            float mx = blk_reduce256(tid < NTOK ? sraw : -1e30f, true, red);
            float p = 0.f;
            if (tid < NTOK) { p = __expf(sraw - mx); scores[tid] = p; }
            denom = blk_reduce256(p, false, red);
        }
        float inv = 1.0f / denom;

        int ch = tid >> 6, d = tid & 63;
        float a0 = 0.f;
        int m0 = ch * 50, m1 = m0 + 50; if (m1 > NTOK) m1 = NTOK;
        #pragma unroll 4
        for (int m = m0; m < m1; m++) a0 = fmaf(scores[m], Vs[m * HD + d], a0);
        part[ch * 64 + d] = a0;
        __syncthreads();
        if (tid < 64) {
            float t = part[tid] + part[64 + tid] + part[128 + tid] + part[192 + tid];
            o[(long)(b * NTOK + n) * DIM + hh * HD + tid] = t * inv;
        }
        __syncthreads();
    }
}

// ---------------- host ----------------
static inline dim3 gemm_grid(int M, int N) {
    return dim3((N + BN - 1) / BN, (M + BM - 1) / BM);
}

extern "C" void kernel_launch(void* const* d_in, const int* in_sizes, int n_in,
                              void* d_out, int out_size) {
    const float* x        = (const float*)d_in[0];
    const float* patch_w  = (const float*)d_in[1];
    const float* patch_b  = (const float*)d_in[2];
    const float* cls_tok  = (const float*)d_in[3];
    const float* pos_emb  = (const float*)d_in[4];
    const float* ln1_w    = (const float*)d_in[5];
    const float* ln1_b    = (const float*)d_in[6];
    const float* qkv_w    = (const float*)d_in[7];
    const float* proj_w   = (const float*)d_in[8];
    const float* proj_b   = (const float*)d_in[9];
    const float* ln2_w    = (const float*)d_in[10];
    const float* ln2_b    = (const float*)d_in[11];
    const float* mlp_w1   = (const float*)d_in[12];
    const float* mlp_b1   = (const float*)d_in[13];
    const float* mlp_w2   = (const float*)d_in[14];
    const float* mlp_b2   = (const float*)d_in[15];
    const float* alpha    = (const float*)d_in[16];
    const float* beta     = (const float*)d_in[17];
    const float* gamma    = (const float*)d_in[18];
    const float* norm_w   = (const float*)d_in[19];
    const float* norm_b   = (const float*)d_in[20];
    const float* head_w   = (const float*)d_in[21];
    const float* head_b   = (const float*)d_in[22];
    float* out = (float*)d_out;

    float *ph, *hh, *lnb, *qkvb, *ob, *mb, *clsb;
    cudaGetSymbolAddress((void**)&ph,   g_patches);
    cudaGetSymbolAddress((void**)&hh,   g_h);
    cudaGetSymbolAddress((void**)&lnb,  g_ln);
    cudaGetSymbolAddress((void**)&qkvb, g_qkv);
    cudaGetSymbolAddress((void**)&ob,   g_attno);
    cudaGetSymbolAddress((void**)&mb,   g_mlp);
    cudaGetSymbolAddress((void**)&clsb, g_cls);

    const int attn_smem = ATTN_SMEM_FLOATS * sizeof(float);
    cudaFuncSetAttribute(attn_kernel, cudaFuncAttributeMaxDynamicSharedMemorySize, attn_smem);

    // 1) patchify + embed
    {
        int total = PROWS * DIM;
        gather_patches_kernel<<<(total + 255) / 256, 256>>>(x, ph);
        gemm_tc_kernel<<<gemm_grid(PROWS, DIM), 256>>>(ph, patch_w, patch_b, nullptr,
                                                       ob /*tok scratch*/, PROWS, DIM, DIM, 0);
        int tot2 = ROWS * DIM;
        embed_kernel<<<(tot2 + 255) / 256, 256>>>(ob, cls_tok, pos_emb, hh);
    }

    // 2) transformer layers
    for (int i = 0; i < DEPTH; i++) {
        int poly = (i % 2 == 0) ? 1 : 0;   // MASK = (T,F,T,F,...)
        ln_kernel<<<ROWS, 256>>>(hh, DIM, ln1_w + (long)i * DIM, ln1_b + (long)i * DIM, lnb);
        gemm_tc_kernel<<<gemm_grid(ROWS, 3 * DIM), 256>>>(lnb, qkv_w + (long)i * 3 * DIM * DIM,
                                                          nullptr, nullptr, qkvb,
                                                          ROWS, 3 * DIM, DIM, 0);
        attn_kernel<<<BATCH * HEADS, 256, attn_smem>>>(qkvb, ob,
                                                       alpha + (long)i * HEADS,
                                                       beta  + (long)i * HEADS,
                                                       gamma + (long)i * HEADS, poly);
        gemm_tc_kernel<<<gemm_grid(ROWS, DIM), 256>>>(ob, proj_w + (long)i * DIM * DIM,
                                                      proj_b + (long)i * DIM, hh, hh,
                                                      ROWS, DIM, DIM, 0);
        ln_kernel<<<ROWS, 256>>>(hh, DIM, ln2_w + (long)i * DIM, ln2_b + (long)i * DIM, lnb);
        gemm_tc_kernel<<<gemm_grid(ROWS, MLPD), 256>>>(lnb, mlp_w1 + (long)i * MLPD * DIM,
                                                       mlp_b1 + (long)i * MLPD, nullptr, mb,
                                                       ROWS, MLPD, DIM, 1 /*gelu*/);
        gemm_tc_kernel<<<gemm_grid(ROWS, DIM), 256>>>(mb, mlp_w2 + (long)i * DIM * MLPD,
                                                      mlp_b2 + (long)i * DIM, hh, hh,
                                                      ROWS, DIM, MLPD, 0);
    }

    // 3) final LN on cls rows + head
    ln_kernel<<<BATCH, 256>>>(hh, (long)NTOK * DIM, norm_w, norm_b, clsb);
    gemm_tc_kernel<<<gemm_grid(BATCH, 1000), 256>>>(clsb, head_w, head_b, nullptr, out,
                                                    BATCH, 1000, DIM, 0);
}